// round 16
// baseline (speedup 1.0000x reference)
#include <cuda_runtime.h>
#include <cuda_fp16.h>
#include <cuda_bf16.h>

#define N_NODES 10000
#define NQUERY  65536

// fp16 copies of the three node tables, rebuilt each launch (7.5 MB, L2-resident)
__device__ __half2 g_posh[N_NODES * 64];
__device__ __half2 g_sfh [N_NODES * 64];
__device__ __half2 g_dfh [N_NODES * 64];

__global__ __launch_bounds__(256)
void cvt_kernel(const float* __restrict__ position,
                const float* __restrict__ src_field,
                const float* __restrict__ dst_field)
{
    const int i = blockIdx.x * blockDim.x + threadIdx.x;   // one float4 per thread
    if (i < N_NODES * 32) {
        float4 v = __ldg(&((const float4*)position)[i]);
        g_posh[i * 2 + 0] = __floats2half2_rn(v.x, v.y);
        g_posh[i * 2 + 1] = __floats2half2_rn(v.z, v.w);
        v = __ldg(&((const float4*)src_field)[i]);
        g_sfh[i * 2 + 0] = __floats2half2_rn(v.x, v.y);
        g_sfh[i * 2 + 1] = __floats2half2_rn(v.z, v.w);
        v = __ldg(&((const float4*)dst_field)[i]);
        g_dfh[i * 2 + 0] = __floats2half2_rn(v.x, v.y);
        g_dfh[i * 2 + 1] = __floats2half2_rn(v.z, v.w);
    }
}

#define H2REF(x) (*(const __half2*)&(x))

__device__ __forceinline__ __half2 shfl_xor_h2(unsigned mask, __half2 v, int m)
{
    unsigned u = *(unsigned*)&v;
    u = __shfl_xor_sync(mask, u, m);
    return *(__half2*)&u;
}

// packed (dot_partial, n2_partial) over this lane's 8 dims
__device__ __forceinline__ __half2 sample_h(const uint4& b, const uint4& f, const uint4& p)
{
    const __half2 d0 = __hsub2(H2REF(b.x), H2REF(p.x));
    const __half2 d1 = __hsub2(H2REF(b.y), H2REF(p.y));
    const __half2 d2 = __hsub2(H2REF(b.z), H2REF(p.z));
    const __half2 d3 = __hsub2(H2REF(b.w), H2REF(p.w));
    __half2 dh = __hmul2(d0, H2REF(f.x));
    dh = __hfma2(d1, H2REF(f.y), dh);
    dh = __hfma2(d2, H2REF(f.z), dh);
    dh = __hfma2(d3, H2REF(f.w), dh);
    __half2 nh = __hmul2(d0, d0);
    nh = __hfma2(d1, d1, nh);
    nh = __hfma2(d2, d2, nh);
    nh = __hfma2(d3, d3, nh);
    return __hadd2(__lows2half2(dh, nh), __highs2half2(dh, nh));
}

__global__ __launch_bounds__(256, 6)
void madgraph_kernel(const int* __restrict__ src,
                     const int* __restrict__ dst,
                     const int* __restrict__ mid0,
                     const int* __restrict__ mid1,
                     const float* __restrict__ position,
                     const float* __restrict__ src_field,
                     const float* __restrict__ dst_field,
                     const float* __restrict__ unc,
                     const float* __restrict__ edge,
                     float* __restrict__ out)
{
    const unsigned FULL = 0xFFFFFFFFu;
    const int warp = (blockIdx.x * blockDim.x + threadIdx.x) >> 5;
    const int lane = threadIdx.x & 31;
    const int hl   = lane & 15;          // lane within half-warp
    const int hsel = lane & 16;          // 0 = query A, 16 = query B
    const int n    = warp * 2 + (hsel >> 4);

    const int s_node = __ldg(&src[n]);
    const int d_node = __ldg(&dst[n]);

    // Every lane owns one sample of its query: hl<8 -> mid0[hl], else mid1[hl-8].
    const int m_own = (hl < 8) ? __ldg(&mid0[n * 8 + hl])
                               : __ldg(&mid1[n * 8 + (hl - 8)]);

    // Edge value (400MB DRAM table): evict-first, issue ASAP.
    const int eidx = (hl < 8) ? (m_own * N_NODES + d_node)    // edge[mid0[s], dst]
                              : (s_node * N_NODES + m_own);   // edge[src, mid1[s]]
    const float ev = __ldcs(&edge[eidx]);
    const float u  = __ldg(unc);

    // Row m of a table = uint4 indices [m*16 .. m*16+15]; lane owns dims [8*hl..8*hl+7].
    const uint4* posh4 = (const uint4*)g_posh;
    const uint4* sfh4  = (const uint4*)g_sfh;
    const uint4* dfh4  = (const uint4*)g_dfh;

    __half2 H1[8], G[8];

    // ---- pass 1: samples 0..7 (base = pos[src], field = dst_field[dst]) ----
    {
        const uint4 b = posh4[s_node * 16 + hl];
        const uint4 f = dfh4 [d_node * 16 + hl];
        #pragma unroll
        for (int c = 0; c < 2; ++c) {
            int mm[4]; uint4 pm[4];
            #pragma unroll
            for (int j = 0; j < 4; ++j)
                mm[j] = __shfl_sync(FULL, m_own, (c * 4 + j) + hsel);
            #pragma unroll
            for (int j = 0; j < 4; ++j)
                pm[j] = posh4[mm[j] * 16 + hl];
            #pragma unroll
            for (int j = 0; j < 4; ++j)
                H1[c * 4 + j] = sample_h(b, f, pm[j]);
        }
    }

    // ---- pass 2: samples 8..15 (base = pos[dst], field = src_field[src]) ----
    {
        const uint4 b = posh4[d_node * 16 + hl];
        const uint4 f = sfh4 [s_node * 16 + hl];
        #pragma unroll
        for (int c = 0; c < 2; ++c) {
            int mm[4]; uint4 pm[4];
            #pragma unroll
            for (int j = 0; j < 4; ++j)
                mm[j] = __shfl_sync(FULL, m_own, (8 + c * 4 + j) + hsel);
            #pragma unroll
            for (int j = 0; j < 4; ++j)
                pm[j] = posh4[mm[j] * 16 + hl];
            #pragma unroll
            for (int j = 0; j < 4; ++j)
                G[c * 4 + j] = sample_h(b, f, pm[j]);
        }
    }

    // ---- 16-value butterfly within each 16-lane half (identity mapping) ----
    // Stage m=8 fused with the pass1/pass2 merge: value index bit3 = lane bit3.
    __half2 Hc[8];
    {
        const bool up = (lane & 8) != 0;
        #pragma unroll
        for (int j = 0; j < 8; ++j) {
            const __half2 send = up ? H1[j] : G[j];
            const __half2 keep = up ? G[j] : H1[j];
            Hc[j] = __hadd2(keep, shfl_xor_h2(FULL, send, 8));
        }
    }
    // Stage m=4 (packed fp16; partial sums still small)
    {
        const bool up = (lane & 4) != 0;
        #pragma unroll
        for (int j = 0; j < 4; ++j) {
            const __half2 send = up ? Hc[j] : Hc[j + 4];
            const __half2 keep = up ? Hc[j + 4] : Hc[j];
            Hc[j] = __hadd2(keep, shfl_xor_h2(FULL, send, 4));
        }
    }
    // Unpack to fp32 for the last two stages (values get large).
    float2 F[4];
    #pragma unroll
    for (int j = 0; j < 4; ++j) F[j] = __half22float2(Hc[j]);
    {
        const bool up = (lane & 2) != 0;
        #pragma unroll
        for (int j = 0; j < 2; ++j) {
            const float sx = up ? F[j].x : F[j + 2].x;
            const float sy = up ? F[j].y : F[j + 2].y;
            const float kx = up ? F[j + 2].x : F[j].x;
            const float ky = up ? F[j + 2].y : F[j].y;
            F[j].x = kx + __shfl_xor_sync(FULL, sx, 2);
            F[j].y = ky + __shfl_xor_sync(FULL, sy, 2);
        }
    }
    {
        const bool up = (lane & 1) != 0;
        const float sx = up ? F[0].x : F[1].x;
        const float sy = up ? F[0].y : F[1].y;
        const float kx = up ? F[1].x : F[0].x;
        const float ky = up ? F[1].y : F[0].y;
        F[0].x = kx + __shfl_xor_sync(FULL, sx, 1);
        F[0].y = ky + __shfl_xor_sync(FULL, sy, 1);
    }
    // Lane hl of each half now holds sample hl's (dot, n2); ev is already here.
    const float dot = F[0].x;
    const float n2  = F[0].y;

    const float logit = dot + u * ev;
    const float a     = 1.0f - sqrtf(n2);

    // 16-wide softmax within each half (offsets 8..1 stay inside the half).
    float mx = a;
    #pragma unroll
    for (int o = 8; o > 0; o >>= 1)
        mx = fmaxf(mx, __shfl_xor_sync(FULL, mx, o));

    const float e = __expf(a - mx);
    float num = logit * e;
    float den = e;
    #pragma unroll
    for (int o = 8; o > 0; o >>= 1) {
        num += __shfl_xor_sync(FULL, num, o);
        den += __shfl_xor_sync(FULL, den, o);
    }

    if (hl == 0) out[n] = num / den;
}

extern "C" void kernel_launch(void* const* d_in, const int* in_sizes, int n_in,
                              void* d_out, int out_size)
{
    const int*   src      = (const int*)  d_in[0];
    const int*   dst      = (const int*)  d_in[1];
    const int*   mid0     = (const int*)  d_in[2];
    const int*   mid1     = (const int*)  d_in[3];
    const float* position = (const float*)d_in[4];
    const float* src_f    = (const float*)d_in[5];
    const float* dst_f    = (const float*)d_in[6];
    const float* unc      = (const float*)d_in[7];
    const float* edge     = (const float*)d_in[8];
    float*       out      = (float*)      d_out;

    // Prologue: fp32 -> fp16 tables (stream-ordered before main kernel)
    cvt_kernel<<<(N_NODES * 32 + 255) / 256, 256>>>(position, src_f, dst_f);

    const int blocks = NQUERY / 16;  // 8 warps x 2 queries per 256-thread block
    madgraph_kernel<<<blocks, 256>>>(src, dst, mid0, mid1, position,
                                     src_f, dst_f, unc, edge, out);
}

// round 17
// speedup vs baseline: 1.0539x; 1.0539x over previous
#include <cuda_runtime.h>
#include <cuda_fp16.h>
#include <cuda_bf16.h>

#define N_NODES 10000
#define NQUERY  65536

// fp16 copies of the three node tables, rebuilt each launch (7.5 MB, L2-resident)
__device__ __half2 g_posh[N_NODES * 64];
__device__ __half2 g_sfh [N_NODES * 64];
__device__ __half2 g_dfh [N_NODES * 64];

__global__ __launch_bounds__(256)
void cvt_kernel(const float* __restrict__ position,
                const float* __restrict__ src_field,
                const float* __restrict__ dst_field)
{
    const int i = blockIdx.x * blockDim.x + threadIdx.x;   // one float4 per thread
    if (i < N_NODES * 32) {
        float4 v = __ldg(&((const float4*)position)[i]);
        g_posh[i * 2 + 0] = __floats2half2_rn(v.x, v.y);
        g_posh[i * 2 + 1] = __floats2half2_rn(v.z, v.w);
        v = __ldg(&((const float4*)src_field)[i]);
        g_sfh[i * 2 + 0] = __floats2half2_rn(v.x, v.y);
        g_sfh[i * 2 + 1] = __floats2half2_rn(v.z, v.w);
        v = __ldg(&((const float4*)dst_field)[i]);
        g_dfh[i * 2 + 0] = __floats2half2_rn(v.x, v.y);
        g_dfh[i * 2 + 1] = __floats2half2_rn(v.z, v.w);
    }
}

#define H2REF(x) (*(const __half2*)&(x))

__device__ __forceinline__ __half2 shfl_xor_h2(unsigned mask, __half2 v, int m)
{
    unsigned u = *(unsigned*)&v;
    u = __shfl_xor_sync(mask, u, m);
    return *(__half2*)&u;
}

// packed (dot_partial, n2_partial) over this lane's 8 dims
__device__ __forceinline__ __half2 sample_h(const uint4& b, const uint4& f, const uint4& p)
{
    const __half2 d0 = __hsub2(H2REF(b.x), H2REF(p.x));
    const __half2 d1 = __hsub2(H2REF(b.y), H2REF(p.y));
    const __half2 d2 = __hsub2(H2REF(b.z), H2REF(p.z));
    const __half2 d3 = __hsub2(H2REF(b.w), H2REF(p.w));
    __half2 dh = __hmul2(d0, H2REF(f.x));
    dh = __hfma2(d1, H2REF(f.y), dh);
    dh = __hfma2(d2, H2REF(f.z), dh);
    dh = __hfma2(d3, H2REF(f.w), dh);
    __half2 nh = __hmul2(d0, d0);
    nh = __hfma2(d1, d1, nh);
    nh = __hfma2(d2, d2, nh);
    nh = __hfma2(d3, d3, nh);
    return __hadd2(__lows2half2(dh, nh), __highs2half2(dh, nh));
}

__global__ __launch_bounds__(256, 4)
void madgraph_kernel(const int* __restrict__ src,
                     const int* __restrict__ dst,
                     const int* __restrict__ mid0,
                     const int* __restrict__ mid1,
                     const float* __restrict__ position,
                     const float* __restrict__ src_field,
                     const float* __restrict__ dst_field,
                     const float* __restrict__ unc,
                     const float* __restrict__ edge,
                     float* __restrict__ out)
{
    const unsigned FULL = 0xFFFFFFFFu;
    const int warp = (blockIdx.x * blockDim.x + threadIdx.x) >> 5;
    const int lane = threadIdx.x & 31;
    const int hl   = lane & 15;          // lane within half-warp
    const int hsel = lane & 16;          // 0 = query A, 16 = query B
    const int n    = warp * 2 + (hsel >> 4);

    const int s_node = __ldg(&src[n]);
    const int d_node = __ldg(&dst[n]);

    // Every lane owns one sample of its query: hl<8 -> mid0[hl], else mid1[hl-8].
    const int m_own = (hl < 8) ? __ldg(&mid0[n * 8 + hl])
                               : __ldg(&mid1[n * 8 + (hl - 8)]);

    // Edge value (400MB DRAM table): evict-first, issue ASAP.
    const int eidx = (hl < 8) ? (m_own * N_NODES + d_node)    // edge[mid0[s], dst]
                              : (s_node * N_NODES + m_own);   // edge[src, mid1[s]]
    const float ev = __ldcs(&edge[eidx]);
    const float u  = __ldg(unc);

    // Row m of a table = uint4 indices [m*16 .. m*16+15]; lane owns dims [8*hl..8*hl+7].
    const uint4* posh4 = (const uint4*)g_posh;
    const uint4* sfh4  = (const uint4*)g_sfh;
    const uint4* dfh4  = (const uint4*)g_dfh;

    // Base/field rows for BOTH passes issued up front (adds MLP over pass-1 chain).
    const uint4 b1 = posh4[s_node * 16 + hl];
    const uint4 f1 = dfh4 [d_node * 16 + hl];
    const uint4 b2 = posh4[d_node * 16 + hl];
    const uint4 f2 = sfh4 [s_node * 16 + hl];

    __half2 H1[8], G[8];

    // ---- pass 1: samples 0..7 (base = pos[src], field = dst_field[dst]) ----
    {
        int mm[8];
        #pragma unroll
        for (int j = 0; j < 8; ++j)
            mm[j] = __shfl_sync(FULL, m_own, j + hsel);
        uint4 pm[8];                      // 8 loads issued back-to-back (MLP=8)
        #pragma unroll
        for (int j = 0; j < 8; ++j)
            pm[j] = posh4[mm[j] * 16 + hl];
        #pragma unroll
        for (int j = 0; j < 8; ++j)
            H1[j] = sample_h(b1, f1, pm[j]);
    }

    // ---- pass 2: samples 8..15 (base = pos[dst], field = src_field[src]) ----
    {
        int mm[8];
        #pragma unroll
        for (int j = 0; j < 8; ++j)
            mm[j] = __shfl_sync(FULL, m_own, (8 + j) + hsel);
        uint4 pm[8];
        #pragma unroll
        for (int j = 0; j < 8; ++j)
            pm[j] = posh4[mm[j] * 16 + hl];
        #pragma unroll
        for (int j = 0; j < 8; ++j)
            G[j] = sample_h(b2, f2, pm[j]);
    }

    // ---- 16-value butterfly within each 16-lane half (identity mapping) ----
    // Stage m=8 fused with the pass1/pass2 merge: value index bit3 = lane bit3.
    __half2 Hc[8];
    {
        const bool up = (lane & 8) != 0;
        #pragma unroll
        for (int j = 0; j < 8; ++j) {
            const __half2 send = up ? H1[j] : G[j];
            const __half2 keep = up ? G[j] : H1[j];
            Hc[j] = __hadd2(keep, shfl_xor_h2(FULL, send, 8));
        }
    }
    // Stage m=4 (packed fp16; partial sums still small)
    {
        const bool up = (lane & 4) != 0;
        #pragma unroll
        for (int j = 0; j < 4; ++j) {
            const __half2 send = up ? Hc[j] : Hc[j + 4];
            const __half2 keep = up ? Hc[j + 4] : Hc[j];
            Hc[j] = __hadd2(keep, shfl_xor_h2(FULL, send, 4));
        }
    }
    // Unpack to fp32 for the last two stages (values get large).
    float2 F[4];
    #pragma unroll
    for (int j = 0; j < 4; ++j) F[j] = __half22float2(Hc[j]);
    {
        const bool up = (lane & 2) != 0;
        #pragma unroll
        for (int j = 0; j < 2; ++j) {
            const float sx = up ? F[j].x : F[j + 2].x;
            const float sy = up ? F[j].y : F[j + 2].y;
            const float kx = up ? F[j + 2].x : F[j].x;
            const float ky = up ? F[j + 2].y : F[j].y;
            F[j].x = kx + __shfl_xor_sync(FULL, sx, 2);
            F[j].y = ky + __shfl_xor_sync(FULL, sy, 2);
        }
    }
    {
        const bool up = (lane & 1) != 0;
        const float sx = up ? F[0].x : F[1].x;
        const float sy = up ? F[0].y : F[1].y;
        const float kx = up ? F[1].x : F[0].x;
        const float ky = up ? F[1].y : F[0].y;
        F[0].x = kx + __shfl_xor_sync(FULL, sx, 1);
        F[0].y = ky + __shfl_xor_sync(FULL, sy, 1);
    }
    // Lane hl of each half now holds sample hl's (dot, n2); ev is already here.
    const float dot = F[0].x;
    const float n2  = F[0].y;

    const float logit = dot + u * ev;
    const float a     = 1.0f - sqrtf(n2);

    // 16-wide softmax within each half (offsets 8..1 stay inside the half).
    float mx = a;
    #pragma unroll
    for (int o = 8; o > 0; o >>= 1)
        mx = fmaxf(mx, __shfl_xor_sync(FULL, mx, o));

    const float e = __expf(a - mx);
    float num = logit * e;
    float den = e;
    #pragma unroll
    for (int o = 8; o > 0; o >>= 1) {
        num += __shfl_xor_sync(FULL, num, o);
        den += __shfl_xor_sync(FULL, den, o);
    }

    if (hl == 0) out[n] = num / den;
}

extern "C" void kernel_launch(void* const* d_in, const int* in_sizes, int n_in,
                              void* d_out, int out_size)
{
    const int*   src      = (const int*)  d_in[0];
    const int*   dst      = (const int*)  d_in[1];
    const int*   mid0     = (const int*)  d_in[2];
    const int*   mid1     = (const int*)  d_in[3];
    const float* position = (const float*)d_in[4];
    const float* src_f    = (const float*)d_in[5];
    const float* dst_f    = (const float*)d_in[6];
    const float* unc      = (const float*)d_in[7];
    const float* edge     = (const float*)d_in[8];
    float*       out      = (float*)      d_out;

    // Prologue: fp32 -> fp16 tables (stream-ordered before main kernel)
    cvt_kernel<<<(N_NODES * 32 + 255) / 256, 256>>>(position, src_f, dst_f);

    const int blocks = NQUERY / 16;  // 8 warps x 2 queries per 256-thread block
    madgraph_kernel<<<blocks, 256>>>(src, dst, mid0, mid1, position,
                                     src_f, dst_f, unc, edge, out);
}